// round 3
// baseline (speedup 1.0000x reference)
#include <cuda_runtime.h>
#include <math.h>
#include <stdint.h>

#define SEQ 4096
#define DIM 1024

// ---------------- scratch (allocation-free) ----------------
__device__ float g_Q[(size_t)SEQ * DIM];
__device__ float g_K[(size_t)SEQ * DIM];
__device__ float g_V[(size_t)SEQ * DIM];
__device__ float g_S[(size_t)SEQ * SEQ];

// ---------------- stage geometry ----------------
// K-stage = 32. Smem per stage: A 128x32 x (hi,lo) = 32KB, B 32x128 x (hi,lo) = 32KB.
#define A_STAGE_BYTES 32768
#define STAGE_BYTES   65536
#define SMEM_BYTES    (2 * STAGE_BYTES)

__device__ __forceinline__ uint32_t cvt_tf32(float x) {
    uint32_t u;
    asm("cvt.rna.tf32.f32 %0, %1;" : "=r"(u) : "f"(x));
    return u;
}

__device__ __forceinline__ void mma_tf32(float* c, const uint32_t* a, const uint32_t* b) {
    asm volatile(
        "mma.sync.aligned.m16n8k8.row.col.f32.tf32.tf32.f32 "
        "{%0,%1,%2,%3}, {%4,%5,%6,%7}, {%8,%9}, {%0,%1,%2,%3};"
        : "+f"(c[0]), "+f"(c[1]), "+f"(c[2]), "+f"(c[3])
        : "r"(a[0]), "r"(a[1]), "r"(a[2]), "r"(a[3]), "r"(b[0]), "r"(b[1]));
}

// ---------------------------------------------------------------------------
// 3xTF32 tensor-core GEMM:
//   TRANS_B = 0 : C[M,N] = alpha * A[M,K] @ B[K,N]      (B row-major [K,N])
//   TRANS_B = 1 : C[M,N] = alpha * A[M,K] @ B[N,K]^T    (B row-major [N,K])
// CTA tile 128x128, 256 threads (8 warps, 2M x 4N), K-stage 32, double buffer.
// Smem holds hi/lo tf32 fragments in mma-fragment-major layout:
//   A tile (mt 0..7, kc 0..3): off = (mt*4+kc)*1024 + term*512 + lane*16 + reg*4
//   B tile (nt 0..15, kc 0..3): off = (nt*4+kc)*512  + term*256 + lane*8  + reg*4
// ---------------------------------------------------------------------------
template <int TRANS_B>
__global__ __launch_bounds__(256, 1)
void mm3tf32(const float* __restrict__ A, const float* __restrict__ B,
             float* __restrict__ C, int M, int N, int K, float alpha)
{
    extern __shared__ char smem[];
    const int tid    = threadIdx.x;
    const int lane   = tid & 31;
    const int wid    = tid >> 5;
    const int warp_m = wid & 1;   // 0..1 -> 64 rows
    const int warp_n = wid >> 1;  // 0..3 -> 32 cols
    const int bm = blockIdx.y * 128;
    const int bn = blockIdx.x * 128;

    float acc[4][4][4];
#pragma unroll
    for (int i = 0; i < 4; i++)
#pragma unroll
        for (int j = 0; j < 4; j++)
#pragma unroll
            for (int r = 0; r < 4; r++) acc[i][j][r] = 0.0f;

    const int nstages = K >> 5;

    float4 ga[4], gb[4];

    // ---- global load of stage kt into registers ----
    auto load_stage = [&](int s) {
        const int kt = s << 5;
#pragma unroll
        for (int it = 0; it < 4; it++) {
            const int idx = tid + it * 256;
            const int row = idx >> 3, c0 = (idx & 7) * 4;
            ga[it] = *reinterpret_cast<const float4*>(&A[(size_t)(bm + row) * K + kt + c0]);
        }
        if (TRANS_B == 0) {
#pragma unroll
            for (int it = 0; it < 4; it++) {
                const int idx = tid + it * 256;
                const int kr = idx >> 5, n0 = (idx & 31) * 4;
                gb[it] = *reinterpret_cast<const float4*>(&B[(size_t)(kt + kr) * N + bn + n0]);
            }
        } else {
#pragma unroll
            for (int it = 0; it < 4; it++) {
                const int idx = tid + it * 256;
                const int nr = idx >> 3, k0 = (idx & 7) * 4;
                gb[it] = *reinterpret_cast<const float4*>(&B[(size_t)(bn + nr) * K + kt + k0]);
            }
        }
    };

    // ---- convert to hi/lo tf32 and store into smem buffer ----
    auto store_stage = [&](int buf) {
        char* abuf = smem + buf * STAGE_BYTES;
        char* bbuf = abuf + A_STAGE_BYTES;
        // A: element (row, col) -> tile(mt= row>>4, kc= col>>3),
        //    lane=(row&7)*4+(col&3), reg=((row>>3)&1)+2*((col>>2)&1)
#pragma unroll
        for (int it = 0; it < 4; it++) {
            const int idx = tid + it * 256;
            const int row = idx >> 3, c0 = (idx & 7) * 4;
            const int mt = row >> 4, rr = row & 15, kc = c0 >> 3;
            const int reg = (rr >> 3) + ((c0 & 4) >> 1);  // + 2*((c0&7)>=4)
            const int base = (mt * 4 + kc) * 1024 + ((rr & 7) * 4) * 16 + reg * 4;
            const float* v = &ga[it].x;
#pragma unroll
            for (int j = 0; j < 4; j++) {
                const uint32_t hi = cvt_tf32(v[j]);
                const uint32_t lo = cvt_tf32(v[j] - __uint_as_float(hi));
                *reinterpret_cast<uint32_t*>(abuf + base + j * 16)       = hi;
                *reinterpret_cast<uint32_t*>(abuf + base + 512 + j * 16) = lo;
            }
        }
        // B: element (k, n) -> tile(nt= n>>3, kc= k>>3),
        //    lane=(n&7)*4+(k&3), reg=(k>>2)&1
        if (TRANS_B == 0) {
#pragma unroll
            for (int it = 0; it < 4; it++) {
                const int idx = tid + it * 256;
                const int kr = idx >> 5, n0 = (idx & 31) * 4;
                const int kc = kr >> 3, kk = kr & 7;
                const int reg = kk >> 2, klane = kk & 3;
                const float* v = &gb[it].x;
#pragma unroll
                for (int j = 0; j < 4; j++) {
                    const int n = n0 + j;
                    const int off = ((n >> 3) * 4 + kc) * 512 + ((n & 7) * 4 + klane) * 8 + reg * 4;
                    const uint32_t hi = cvt_tf32(v[j]);
                    const uint32_t lo = cvt_tf32(v[j] - __uint_as_float(hi));
                    *reinterpret_cast<uint32_t*>(bbuf + off)       = hi;
                    *reinterpret_cast<uint32_t*>(bbuf + off + 256) = lo;
                }
            }
        } else {
#pragma unroll
            for (int it = 0; it < 4; it++) {
                const int idx = tid + it * 256;
                const int nr = idx >> 3, k0 = (idx & 7) * 4;
                const int nt = nr >> 3, nn = nr & 7, kc = k0 >> 3;
                const int reg = (k0 & 4) >> 2;
                const int base = (nt * 4 + kc) * 512 + (nn * 4) * 8 + reg * 4;
                const float* v = &gb[it].x;
#pragma unroll
                for (int j = 0; j < 4; j++) {
                    const uint32_t hi = cvt_tf32(v[j]);
                    const uint32_t lo = cvt_tf32(v[j] - __uint_as_float(hi));
                    *reinterpret_cast<uint32_t*>(bbuf + base + j * 8)       = hi;
                    *reinterpret_cast<uint32_t*>(bbuf + base + 256 + j * 8) = lo;
                }
            }
        }
    };

    // ---- compute one stage from smem buffer ----
    auto compute_stage = [&](int buf) {
        const char* abuf = smem + buf * STAGE_BYTES;
        const char* bbuf = abuf + A_STAGE_BYTES;
#pragma unroll
        for (int kc = 0; kc < 4; kc++) {
            uint32_t af[2][4][4], bf[2][4][2];
#pragma unroll
            for (int mt = 0; mt < 4; mt++) {
                const int t = ((warp_m * 4 + mt) * 4 + kc) * 1024 + lane * 16;
#pragma unroll
                for (int term = 0; term < 2; term++) {
                    const float4 v = *reinterpret_cast<const float4*>(abuf + t + term * 512);
                    af[term][mt][0] = __float_as_uint(v.x);
                    af[term][mt][1] = __float_as_uint(v.y);
                    af[term][mt][2] = __float_as_uint(v.z);
                    af[term][mt][3] = __float_as_uint(v.w);
                }
            }
#pragma unroll
            for (int nt = 0; nt < 4; nt++) {
                const int t = ((warp_n * 4 + nt) * 4 + kc) * 512 + lane * 8;
#pragma unroll
                for (int term = 0; term < 2; term++) {
                    const float2 v = *reinterpret_cast<const float2*>(bbuf + t + term * 256);
                    bf[term][nt][0] = __float_as_uint(v.x);
                    bf[term][nt][1] = __float_as_uint(v.y);
                }
            }
#pragma unroll
            for (int mt = 0; mt < 4; mt++)
#pragma unroll
                for (int nt = 0; nt < 4; nt++) {
                    mma_tf32(acc[mt][nt], af[0][mt], bf[0][nt]);
                    mma_tf32(acc[mt][nt], af[0][mt], bf[1][nt]);
                    mma_tf32(acc[mt][nt], af[1][mt], bf[0][nt]);
                }
        }
    };

    // ---- pipelined main loop ----
    load_stage(0);
    store_stage(0);
    __syncthreads();
    for (int s = 0; s < nstages; s++) {
        if (s + 1 < nstages) load_stage(s + 1);
        compute_stage(s & 1);
        if (s + 1 < nstages) {
            store_stage((s + 1) & 1);
            __syncthreads();
        }
    }

    // ---- epilogue ----
#pragma unroll
    for (int mt = 0; mt < 4; mt++) {
        const int row0 = bm + warp_m * 64 + mt * 16 + (lane >> 2);
#pragma unroll
        for (int nt = 0; nt < 4; nt++) {
            const int col0 = bn + warp_n * 32 + nt * 8 + (lane & 3) * 2;
            float2 lo, hi;
            lo.x = alpha * acc[mt][nt][0];
            lo.y = alpha * acc[mt][nt][1];
            hi.x = alpha * acc[mt][nt][2];
            hi.y = alpha * acc[mt][nt][3];
            *reinterpret_cast<float2*>(&C[(size_t)row0 * N + col0])       = lo;
            *reinterpret_cast<float2*>(&C[(size_t)(row0 + 8) * N + col0]) = hi;
        }
    }
}

// ---------------------------------------------------------------------------
// Row softmax, in place. One block (256 threads) per row of length n.
// ---------------------------------------------------------------------------
__global__ __launch_bounds__(256)
void softmax_rows(float* __restrict__ S, int n)
{
    __shared__ float red[256];
    const int tid = threadIdx.x;
    float* row = S + (size_t)blockIdx.x * n;

    float m = -INFINITY;
    for (int i = tid; i < n; i += 256) m = fmaxf(m, row[i]);
    red[tid] = m;
    __syncthreads();
    for (int s = 128; s > 0; s >>= 1) {
        if (tid < s) red[tid] = fmaxf(red[tid], red[tid + s]);
        __syncthreads();
    }
    m = red[0];
    __syncthreads();

    float sum = 0.0f;
    for (int i = tid; i < n; i += 256) {
        const float e = expf(row[i] - m);
        row[i] = e;
        sum += e;
    }
    red[tid] = sum;
    __syncthreads();
    for (int s = 128; s > 0; s >>= 1) {
        if (tid < s) red[tid] += red[tid + s];
        __syncthreads();
    }
    const float inv = 1.0f / red[0];
    __syncthreads();

    for (int i = tid; i < n; i += 256) row[i] *= inv;
}

// ---------------------------------------------------------------------------
extern "C" void kernel_launch(void* const* d_in, const int* in_sizes, int n_in,
                              void* d_out, int out_size)
{
    const float* X  = (const float*)d_in[0];
    const float* Wq = (const float*)d_in[1];
    const float* Wk = (const float*)d_in[2];
    const float* Wv = (const float*)d_in[3];
    float* out = (float*)d_out;

    float *Q, *K, *V, *S;
    cudaGetSymbolAddress((void**)&Q, g_Q);
    cudaGetSymbolAddress((void**)&K, g_K);
    cudaGetSymbolAddress((void**)&V, g_V);
    cudaGetSymbolAddress((void**)&S, g_S);

    cudaFuncSetAttribute(mm3tf32<0>, cudaFuncAttributeMaxDynamicSharedMemorySize, SMEM_BYTES);
    cudaFuncSetAttribute(mm3tf32<1>, cudaFuncAttributeMaxDynamicSharedMemorySize, SMEM_BYTES);

    const dim3 blk(256);
    const dim3 gp(DIM / 128, SEQ / 128);     // (8, 32)
    const dim3 gs(SEQ / 128, SEQ / 128);     // (32, 32)

    // Projections (NN)
    mm3tf32<0><<<gp, blk, SMEM_BYTES>>>(X, Wq, Q, SEQ, DIM, DIM, 1.0f);
    mm3tf32<0><<<gp, blk, SMEM_BYTES>>>(X, Wk, K, SEQ, DIM, DIM, 1.0f);
    mm3tf32<0><<<gp, blk, SMEM_BYTES>>>(X, Wv, V, SEQ, DIM, DIM, 1.0f);

    // S = (Q @ K^T) * 1/sqrt(DIM)  (NT)
    mm3tf32<1><<<gs, blk, SMEM_BYTES>>>(Q, K, S, SEQ, SEQ, DIM, 0.03125f);

    // softmax rows
    softmax_rows<<<SEQ, blk>>>(S, SEQ);

    // out = S @ V  (NN)
    mm3tf32<0><<<gp, blk, SMEM_BYTES>>>(S, V, out, SEQ, DIM, SEQ, 1.0f);
}

// round 4
// speedup vs baseline: 2.1683x; 2.1683x over previous
#include <cuda_runtime.h>
#include <math.h>
#include <stdint.h>

#define SEQ 4096
#define DIM 1024

// ---------------- scratch (allocation-free) ----------------
__device__ float g_Q [(size_t)SEQ * DIM];
__device__ float g_K [(size_t)SEQ * DIM];
__device__ float g_V [(size_t)SEQ * DIM];
__device__ float g_Vt[(size_t)SEQ * DIM];
__device__ float g_S [(size_t)SEQ * SEQ];
__device__ float g_Wt[3 * (size_t)DIM * DIM];

// CTA tile 128(M) x 256(N), K-stage 32, fp32 fragments in smem, double buffer.
// Stage: A 128x32 fp32 = 16KB, B 256x32 fp32 = 32KB -> 48KB; x2 = 96KB.
#define STAGE_BYTES 49152
#define A_BYTES     16384
#define SMEM_BYTES  (2 * STAGE_BYTES)

__device__ __forceinline__ uint32_t cvt_tf32(float x) {
    uint32_t u;
    asm("cvt.rna.tf32.f32 %0, %1;" : "=r"(u) : "f"(x));
    return u;
}
__device__ __forceinline__ void split2(float x, uint32_t& h, uint32_t& l) {
    h = cvt_tf32(x);
    l = cvt_tf32(x - __uint_as_float(h));
}
__device__ __forceinline__ void mma_tf32(float* c, const uint32_t* a, const uint32_t* b) {
    asm volatile(
        "mma.sync.aligned.m16n8k8.row.col.f32.tf32.tf32.f32 "
        "{%0,%1,%2,%3}, {%4,%5,%6,%7}, {%8,%9}, {%0,%1,%2,%3};"
        : "+f"(c[0]), "+f"(c[1]), "+f"(c[2]), "+f"(c[3])
        : "r"(a[0]), "r"(a[1]), "r"(a[2]), "r"(a[3]), "r"(b[0]), "r"(b[1]));
}

// ---------------------------------------------------------------------------
// 3xTF32 NT GEMM: C[M,N] = alpha * A[M,K] @ B[N,K]^T  (A,B row-major, ld=K)
// 256 threads = 8 warps (2M x 4N), warp tile 64x64.
// Smem fragment-major fp32 layout:
//  A tile(mt 0..7, kc 0..3) 16x8 fp32 = 512B at (mt*4+kc)*512;
//    element(rr,c): lane=(rr&7)*4+(c&3), reg=(rr>>3)+2*(c>>2);
//    physical 16B block for logical lane L at ((L^kc)<<4), word reg.
//  B pair tile(p 0..15, kc 0..3) = two 8x8 tiles interleaved, 512B at
//    A_BYTES + (p*4+kc)*512; element(n local nn, k c, sub-tile t):
//    lane=nn*4+(c&3), block ((lane^kc)<<4), word t*2 + (c>>2).
// ---------------------------------------------------------------------------
__global__ __launch_bounds__(256, 1)
void mm3nt(const float* __restrict__ A, const float* __restrict__ B,
           float* __restrict__ C, int M, int N, int K, float alpha)
{
    extern __shared__ char smem[];
    const int tid    = threadIdx.x;
    const int lane   = tid & 31;
    const int wid    = tid >> 5;
    const int warp_m = wid & 1;
    const int warp_n = wid >> 1;
    const int bm = blockIdx.y * 128;
    const int bn = blockIdx.x * 256;

    float acc[4][8][4];
#pragma unroll
    for (int i = 0; i < 4; i++)
#pragma unroll
        for (int j = 0; j < 8; j++)
#pragma unroll
            for (int r = 0; r < 4; r++) acc[i][j][r] = 0.0f;

    const int nstages = K >> 5;
    float4 ga[4], gb[8];

    auto load_stage = [&](int s) {
        const int kt = s << 5;
#pragma unroll
        for (int it = 0; it < 4; it++) {
            const int idx = tid + it * 256;
            ga[it] = *reinterpret_cast<const float4*>(
                &A[(size_t)(bm + (idx >> 3)) * K + kt + (idx & 7) * 4]);
        }
#pragma unroll
        for (int it = 0; it < 8; it++) {
            const int idx = tid + it * 256;
            gb[it] = *reinterpret_cast<const float4*>(
                &B[(size_t)(bn + (idx >> 3)) * K + kt + (idx & 7) * 4]);
        }
    };

    auto store_stage = [&](int buf) {
        char* ab = smem + buf * STAGE_BYTES;
        char* bb = ab + A_BYTES;
#pragma unroll
        for (int it = 0; it < 4; it++) {
            const int idx = tid + it * 256;
            const int row = idx >> 3, c0 = (idx & 7) * 4;
            const int mt = row >> 4, rr = row & 15, kc = c0 >> 3;
            const int reg = (rr >> 3) + ((c0 >> 1) & 2);   // (rr>>3) + 2*((c0>>2)&1)
            const int L0  = (rr & 7) * 4;
            const int base = (mt * 4 + kc) * 512;
            const float* v = &ga[it].x;
#pragma unroll
            for (int j = 0; j < 4; j++)
                *reinterpret_cast<float*>(ab + base + (((L0 + j) ^ kc) << 4) + reg * 4) = v[j];
        }
#pragma unroll
        for (int it = 0; it < 8; it++) {
            const int idx = tid + it * 256;
            const int nr = idx >> 3, k0 = (idx & 7) * 4;
            const int pair = nr >> 4, t = (nr >> 3) & 1, nn = nr & 7;
            const int kc = k0 >> 3, reg = (k0 >> 2) & 1;
            const int base = (pair * 4 + kc) * 512;
            const int word = t * 2 + reg;
            const float* v = &gb[it].x;
#pragma unroll
            for (int j = 0; j < 4; j++)
                *reinterpret_cast<float*>(bb + base + (((nn * 4 + j) ^ kc) << 4) + word * 4) = v[j];
        }
    };

    auto compute_stage = [&](int buf) {
        const char* ab = smem + buf * STAGE_BYTES;
        const char* bb = ab + A_BYTES;
#pragma unroll
        for (int kc = 0; kc < 4; kc++) {
            uint32_t ahi[4][4], alo[4][4];
#pragma unroll
            for (int mt = 0; mt < 4; mt++) {
                const float4 v = *reinterpret_cast<const float4*>(
                    ab + ((warp_m * 4 + mt) * 4 + kc) * 512 + ((lane ^ kc) << 4));
                split2(v.x, ahi[mt][0], alo[mt][0]);
                split2(v.y, ahi[mt][1], alo[mt][1]);
                split2(v.z, ahi[mt][2], alo[mt][2]);
                split2(v.w, ahi[mt][3], alo[mt][3]);
            }
#pragma unroll
            for (int h = 0; h < 2; h++) {
                uint32_t bhi[4][2], blo[4][2];
#pragma unroll
                for (int pp = 0; pp < 2; pp++) {
                    const int p = warp_n * 4 + h * 2 + pp;
                    const float4 v = *reinterpret_cast<const float4*>(
                        bb + (p * 4 + kc) * 512 + ((lane ^ kc) << 4));
                    split2(v.x, bhi[pp * 2 + 0][0], blo[pp * 2 + 0][0]);
                    split2(v.y, bhi[pp * 2 + 0][1], blo[pp * 2 + 0][1]);
                    split2(v.z, bhi[pp * 2 + 1][0], blo[pp * 2 + 1][0]);
                    split2(v.w, bhi[pp * 2 + 1][1], blo[pp * 2 + 1][1]);
                }
#pragma unroll
                for (int mt = 0; mt < 4; mt++)
#pragma unroll
                    for (int q = 0; q < 4; q++) {
                        float* a = acc[mt][h * 4 + q];
                        mma_tf32(a, ahi[mt], bhi[q]);
                        mma_tf32(a, ahi[mt], blo[q]);
                        mma_tf32(a, alo[mt], bhi[q]);
                    }
            }
        }
    };

    load_stage(0);
    store_stage(0);
    __syncthreads();
    for (int s = 0; s < nstages; s++) {
        if (s + 1 < nstages) load_stage(s + 1);
        compute_stage(s & 1);
        if (s + 1 < nstages) {
            store_stage((s + 1) & 1);
            __syncthreads();
        }
    }

    // epilogue
#pragma unroll
    for (int mt = 0; mt < 4; mt++) {
        const int row0 = bm + warp_m * 64 + mt * 16 + (lane >> 2);
#pragma unroll
        for (int nt = 0; nt < 8; nt++) {
            const int col0 = bn + warp_n * 64 + nt * 8 + (lane & 3) * 2;
            float2 lo, hi;
            lo.x = alpha * acc[mt][nt][0];
            lo.y = alpha * acc[mt][nt][1];
            hi.x = alpha * acc[mt][nt][2];
            hi.y = alpha * acc[mt][nt][3];
            *reinterpret_cast<float2*>(&C[(size_t)row0 * N + col0])       = lo;
            *reinterpret_cast<float2*>(&C[(size_t)(row0 + 8) * N + col0]) = hi;
        }
    }
}

// ---------------------------------------------------------------------------
// Transpose: dst[c*R + r] = src[r*C + c]
// ---------------------------------------------------------------------------
__global__ __launch_bounds__(256)
void transpose_k(const float* __restrict__ src, float* __restrict__ dst, int R, int C)
{
    __shared__ float t[32][33];
    const int x  = blockIdx.x * 32 + threadIdx.x;
    const int y0 = blockIdx.y * 32 + threadIdx.y;
#pragma unroll
    for (int i = 0; i < 32; i += 8)
        t[threadIdx.y + i][threadIdx.x] = src[(size_t)(y0 + i) * C + x];
    __syncthreads();
    const int ox  = blockIdx.y * 32 + threadIdx.x;
    const int oy0 = blockIdx.x * 32 + threadIdx.y;
#pragma unroll
    for (int i = 0; i < 32; i += 8)
        dst[(size_t)(oy0 + i) * R + ox] = t[threadIdx.x][threadIdx.y + i];
}

// ---------------------------------------------------------------------------
// Row softmax, in place. One block (256 threads) per row of length n.
// ---------------------------------------------------------------------------
__global__ __launch_bounds__(256)
void softmax_rows(float* __restrict__ S, int n)
{
    __shared__ float red[256];
    const int tid = threadIdx.x;
    float* row = S + (size_t)blockIdx.x * n;

    float m = -INFINITY;
    for (int i = tid; i < n; i += 256) m = fmaxf(m, row[i]);
    red[tid] = m;
    __syncthreads();
    for (int s = 128; s > 0; s >>= 1) {
        if (tid < s) red[tid] = fmaxf(red[tid], red[tid + s]);
        __syncthreads();
    }
    m = red[0];
    __syncthreads();

    float sum = 0.0f;
    for (int i = tid; i < n; i += 256) {
        const float e = expf(row[i] - m);
        row[i] = e;
        sum += e;
    }
    red[tid] = sum;
    __syncthreads();
    for (int s = 128; s > 0; s >>= 1) {
        if (tid < s) red[tid] += red[tid + s];
        __syncthreads();
    }
    const float inv = 1.0f / red[0];
    __syncthreads();

    for (int i = tid; i < n; i += 256) row[i] *= inv;
}

// ---------------------------------------------------------------------------
extern "C" void kernel_launch(void* const* d_in, const int* in_sizes, int n_in,
                              void* d_out, int out_size)
{
    const float* X  = (const float*)d_in[0];
    const float* Wq = (const float*)d_in[1];
    const float* Wk = (const float*)d_in[2];
    const float* Wv = (const float*)d_in[3];
    float* out = (float*)d_out;

    float *Q, *K, *V, *Vt, *S, *Wt;
    cudaGetSymbolAddress((void**)&Q,  g_Q);
    cudaGetSymbolAddress((void**)&K,  g_K);
    cudaGetSymbolAddress((void**)&V,  g_V);
    cudaGetSymbolAddress((void**)&Vt, g_Vt);
    cudaGetSymbolAddress((void**)&S,  g_S);
    cudaGetSymbolAddress((void**)&Wt, g_Wt);

    cudaFuncSetAttribute(mm3nt, cudaFuncAttributeMaxDynamicSharedMemorySize, SMEM_BYTES);

    const dim3 blk(256);
    const dim3 tblk(32, 8);

    // 0) W^T (B operands must be [N,K] row-major)
    transpose_k<<<dim3(32, 32), tblk>>>(Wq, Wt,                        DIM, DIM);
    transpose_k<<<dim3(32, 32), tblk>>>(Wk, Wt + (size_t)DIM * DIM,   DIM, DIM);
    transpose_k<<<dim3(32, 32), tblk>>>(Wv, Wt + 2 * (size_t)DIM * DIM, DIM, DIM);

    // 1-3) projections: [4096,1024] = X @ Wt^T  (NT)
    const dim3 gp(DIM / 256, SEQ / 128);   // (4, 32)
    mm3nt<<<gp, blk, SMEM_BYTES>>>(X, Wt,                          Q, SEQ, DIM, DIM, 1.0f);
    mm3nt<<<gp, blk, SMEM_BYTES>>>(X, Wt + (size_t)DIM * DIM,      K, SEQ, DIM, DIM, 1.0f);
    mm3nt<<<gp, blk, SMEM_BYTES>>>(X, Wt + 2 * (size_t)DIM * DIM,  V, SEQ, DIM, DIM, 1.0f);

    // 4) V^T for the AV GEMM
    transpose_k<<<dim3(DIM / 32, SEQ / 32), tblk>>>(V, Vt, SEQ, DIM);

    // 5) S = (Q @ K^T) * 1/sqrt(DIM)
    mm3nt<<<dim3(SEQ / 256, SEQ / 128), blk, SMEM_BYTES>>>(Q, K, S, SEQ, SEQ, DIM, 0.03125f);

    // 6) softmax rows
    softmax_rows<<<SEQ, blk>>>(S, SEQ);

    // 7) out = S @ Vt^T
    mm3nt<<<dim3(DIM / 256, SEQ / 128), blk, SMEM_BYTES>>>(S, Vt, out, SEQ, DIM, SEQ, 1.0f);
}

// round 5
// speedup vs baseline: 2.2326x; 1.0296x over previous
#include <cuda_runtime.h>
#include <math.h>
#include <stdint.h>

#define SEQ 4096
#define DIM 1024

// ---------------- scratch (allocation-free) ----------------
__device__ float g_Q [(size_t)SEQ * DIM];
__device__ float g_K [(size_t)SEQ * DIM];
__device__ float g_V [(size_t)SEQ * DIM];
__device__ float g_Vt[(size_t)SEQ * DIM];
__device__ float g_S [(size_t)SEQ * SEQ];
__device__ float g_Wt[3 * (size_t)DIM * DIM];

// CTA tile 128(M) x 256(N), K-stage 32. Smem holds hi AND lo tf32 planes in
// fragment-major layout, double buffered:
//   stage = A (16KB hi + 16KB lo) + B (32KB hi + 32KB lo) = 96KB; x2 = 192KB.
#define A_PLANE   16384
#define B_PLANE   32768
#define A_BYTES   (2 * A_PLANE)                 // 32KB
#define STAGE_BYTES (A_BYTES + 2 * B_PLANE)     // 96KB
#define SMEM_BYTES  (2 * STAGE_BYTES)           // 192KB

__device__ __forceinline__ uint32_t cvt_tf32(float x) {
    uint32_t u;
    asm("cvt.rna.tf32.f32 %0, %1;" : "=r"(u) : "f"(x));
    return u;
}
__device__ __forceinline__ void split2(float x, uint32_t& h, uint32_t& l) {
    h = cvt_tf32(x);
    l = cvt_tf32(x - __uint_as_float(h));
}
__device__ __forceinline__ void mma_tf32(float* c, const uint32_t* a, const uint32_t* b) {
    asm volatile(
        "mma.sync.aligned.m16n8k8.row.col.f32.tf32.tf32.f32 "
        "{%0,%1,%2,%3}, {%4,%5,%6,%7}, {%8,%9}, {%0,%1,%2,%3};"
        : "+f"(c[0]), "+f"(c[1]), "+f"(c[2]), "+f"(c[3])
        : "r"(a[0]), "r"(a[1]), "r"(a[2]), "r"(a[3]), "r"(b[0]), "r"(b[1]));
}

// ---------------------------------------------------------------------------
// 3xTF32 NT GEMM: C[M,N] = alpha * A[M,K] @ B[N,K]^T  (A,B row-major, ld=K)
// 256 threads = 8 warps (2M x 4N), warp tile 64x64.
// Fragment-major layouts (per plane):
//  A tile(mt 0..7, kc 0..3): 512B at (mt*4+kc)*512;
//    element(rr,c): lane=(rr&7)*4+(c&3), reg=(rr>>3)+2*(c>>2);
//    16B block for logical lane L at ((L^kc)<<4), word = reg.
//  B pair tile(p 0..15, kc 0..3): 512B at (p*4+kc)*512;
//    element(nn,c,sub t): lane=nn*4+(c&3), block ((lane^kc)<<4), word t*2+(c>>2).
// ---------------------------------------------------------------------------
__global__ __launch_bounds__(256, 1)
void mm3nt(const float* __restrict__ A, const float* __restrict__ B,
           float* __restrict__ C, int M, int N, int K, float alpha)
{
    extern __shared__ char smem[];
    const int tid    = threadIdx.x;
    const int lane   = tid & 31;
    const int wid    = tid >> 5;
    const int warp_m = wid & 1;
    const int warp_n = wid >> 1;
    const int bm = blockIdx.y * 128;
    const int bn = blockIdx.x * 256;

    float acc[4][8][4];
#pragma unroll
    for (int i = 0; i < 4; i++)
#pragma unroll
        for (int j = 0; j < 8; j++)
#pragma unroll
            for (int r = 0; r < 4; r++) acc[i][j][r] = 0.0f;

    const int nstages = K >> 5;
    float4 ga[4], gb[8];

    auto load_stage = [&](int s) {
        const int kt = s << 5;
#pragma unroll
        for (int it = 0; it < 4; it++) {
            const int idx = tid + it * 256;
            ga[it] = *reinterpret_cast<const float4*>(
                &A[(size_t)(bm + (idx >> 3)) * K + kt + (idx & 7) * 4]);
        }
#pragma unroll
        for (int it = 0; it < 8; it++) {
            const int idx = tid + it * 256;
            gb[it] = *reinterpret_cast<const float4*>(
                &B[(size_t)(bn + (idx >> 3)) * K + kt + (idx & 7) * 4]);
        }
    };

    auto store_stage = [&](int buf) {
        char* ab = smem + buf * STAGE_BYTES;          // A hi plane
        char* bb = ab + A_BYTES;                      // B hi plane
#pragma unroll
        for (int it = 0; it < 4; it++) {
            const int idx = tid + it * 256;
            const int row = idx >> 3, c0 = (idx & 7) * 4;
            const int mt = row >> 4, rr = row & 15, kc = c0 >> 3;
            const int reg = (rr >> 3) + ((c0 >> 1) & 2);
            const int L0  = (rr & 7) * 4;
            const int base = (mt * 4 + kc) * 512;
            const float* v = &ga[it].x;
#pragma unroll
            for (int j = 0; j < 4; j++) {
                uint32_t h, l;
                split2(v[j], h, l);
                const int off = base + (((L0 + j) ^ kc) << 4) + reg * 4;
                *reinterpret_cast<uint32_t*>(ab + off)           = h;
                *reinterpret_cast<uint32_t*>(ab + off + A_PLANE) = l;
            }
        }
#pragma unroll
        for (int it = 0; it < 8; it++) {
            const int idx = tid + it * 256;
            const int nr = idx >> 3, k0 = (idx & 7) * 4;
            const int pair = nr >> 4, t = (nr >> 3) & 1, nn = nr & 7;
            const int kc = k0 >> 3, reg = (k0 >> 2) & 1;
            const int base = (pair * 4 + kc) * 512;
            const int word = t * 2 + reg;
            const float* v = &gb[it].x;
#pragma unroll
            for (int j = 0; j < 4; j++) {
                uint32_t h, l;
                split2(v[j], h, l);
                const int off = base + (((nn * 4 + j) ^ kc) << 4) + word * 4;
                *reinterpret_cast<uint32_t*>(bb + off)           = h;
                *reinterpret_cast<uint32_t*>(bb + off + B_PLANE) = l;
            }
        }
    };

    auto compute_stage = [&](int buf) {
        const char* ab = smem + buf * STAGE_BYTES;
        const char* bb = ab + A_BYTES;
#pragma unroll
        for (int kc = 0; kc < 4; kc++) {
            uint32_t ahi[4][4], alo[4][4];
#pragma unroll
            for (int mt = 0; mt < 4; mt++) {
                const int off = ((warp_m * 4 + mt) * 4 + kc) * 512 + ((lane ^ kc) << 4);
                const uint4 vh = *reinterpret_cast<const uint4*>(ab + off);
                const uint4 vl = *reinterpret_cast<const uint4*>(ab + off + A_PLANE);
                ahi[mt][0] = vh.x; ahi[mt][1] = vh.y; ahi[mt][2] = vh.z; ahi[mt][3] = vh.w;
                alo[mt][0] = vl.x; alo[mt][1] = vl.y; alo[mt][2] = vl.z; alo[mt][3] = vl.w;
            }
#pragma unroll
            for (int h = 0; h < 2; h++) {
                uint32_t bhi[4][2], blo[4][2];
#pragma unroll
                for (int pp = 0; pp < 2; pp++) {
                    const int p = warp_n * 4 + h * 2 + pp;
                    const int off = (p * 4 + kc) * 512 + ((lane ^ kc) << 4);
                    const uint4 vh = *reinterpret_cast<const uint4*>(bb + off);
                    const uint4 vl = *reinterpret_cast<const uint4*>(bb + off + B_PLANE);
                    bhi[pp * 2 + 0][0] = vh.x; bhi[pp * 2 + 0][1] = vh.y;
                    bhi[pp * 2 + 1][0] = vh.z; bhi[pp * 2 + 1][1] = vh.w;
                    blo[pp * 2 + 0][0] = vl.x; blo[pp * 2 + 0][1] = vl.y;
                    blo[pp * 2 + 1][0] = vl.z; blo[pp * 2 + 1][1] = vl.w;
                }
                // term-major: 16 independent MMAs per term
#pragma unroll
                for (int mt = 0; mt < 4; mt++)
#pragma unroll
                    for (int q = 0; q < 4; q++)
                        mma_tf32(acc[mt][h * 4 + q], ahi[mt], bhi[q]);
#pragma unroll
                for (int mt = 0; mt < 4; mt++)
#pragma unroll
                    for (int q = 0; q < 4; q++)
                        mma_tf32(acc[mt][h * 4 + q], ahi[mt], blo[q]);
#pragma unroll
                for (int mt = 0; mt < 4; mt++)
#pragma unroll
                    for (int q = 0; q < 4; q++)
                        mma_tf32(acc[mt][h * 4 + q], alo[mt], bhi[q]);
            }
        }
    };

    load_stage(0);
    store_stage(0);
    __syncthreads();
    for (int s = 0; s < nstages; s++) {
        if (s + 1 < nstages) load_stage(s + 1);
        compute_stage(s & 1);
        if (s + 1 < nstages) {
            store_stage((s + 1) & 1);
            __syncthreads();
        }
    }

    // epilogue
#pragma unroll
    for (int mt = 0; mt < 4; mt++) {
        const int row0 = bm + warp_m * 64 + mt * 16 + (lane >> 2);
#pragma unroll
        for (int nt = 0; nt < 8; nt++) {
            const int col0 = bn + warp_n * 64 + nt * 8 + (lane & 3) * 2;
            float2 lo, hi;
            lo.x = alpha * acc[mt][nt][0];
            lo.y = alpha * acc[mt][nt][1];
            hi.x = alpha * acc[mt][nt][2];
            hi.y = alpha * acc[mt][nt][3];
            *reinterpret_cast<float2*>(&C[(size_t)row0 * N + col0])       = lo;
            *reinterpret_cast<float2*>(&C[(size_t)(row0 + 8) * N + col0]) = hi;
        }
    }
}

// ---------------------------------------------------------------------------
// Transpose: dst[c*R + r] = src[r*C + c]
// ---------------------------------------------------------------------------
__global__ __launch_bounds__(256)
void transpose_k(const float* __restrict__ src, float* __restrict__ dst, int R, int C)
{
    __shared__ float t[32][33];
    const int x  = blockIdx.x * 32 + threadIdx.x;
    const int y0 = blockIdx.y * 32 + threadIdx.y;
#pragma unroll
    for (int i = 0; i < 32; i += 8)
        t[threadIdx.y + i][threadIdx.x] = src[(size_t)(y0 + i) * C + x];
    __syncthreads();
    const int ox  = blockIdx.y * 32 + threadIdx.x;
    const int oy0 = blockIdx.x * 32 + threadIdx.y;
#pragma unroll
    for (int i = 0; i < 32; i += 8)
        dst[(size_t)(oy0 + i) * R + ox] = t[threadIdx.x][threadIdx.y + i];
}

// ---------------------------------------------------------------------------
// Row softmax, in place. One block (256 threads) per row of length n.
// ---------------------------------------------------------------------------
__global__ __launch_bounds__(256)
void softmax_rows(float* __restrict__ S, int n)
{
    __shared__ float red[256];
    const int tid = threadIdx.x;
    float* row = S + (size_t)blockIdx.x * n;

    float m = -INFINITY;
    for (int i = tid; i < n; i += 256) m = fmaxf(m, row[i]);
    red[tid] = m;
    __syncthreads();
    for (int s = 128; s > 0; s >>= 1) {
        if (tid < s) red[tid] = fmaxf(red[tid], red[tid + s]);
        __syncthreads();
    }
    m = red[0];
    __syncthreads();

    float sum = 0.0f;
    for (int i = tid; i < n; i += 256) {
        const float e = expf(row[i] - m);
        row[i] = e;
        sum += e;
    }
    red[tid] = sum;
    __syncthreads();
    for (int s = 128; s > 0; s >>= 1) {
        if (tid < s) red[tid] += red[tid + s];
        __syncthreads();
    }
    const float inv = 1.0f / red[0];
    __syncthreads();

    for (int i = tid; i < n; i += 256) row[i] *= inv;
}

// ---------------------------------------------------------------------------
extern "C" void kernel_launch(void* const* d_in, const int* in_sizes, int n_in,
                              void* d_out, int out_size)
{
    const float* X  = (const float*)d_in[0];
    const float* Wq = (const float*)d_in[1];
    const float* Wk = (const float*)d_in[2];
    const float* Wv = (const float*)d_in[3];
    float* out = (float*)d_out;

    float *Q, *K, *V, *Vt, *S, *Wt;
    cudaGetSymbolAddress((void**)&Q,  g_Q);
    cudaGetSymbolAddress((void**)&K,  g_K);
    cudaGetSymbolAddress((void**)&V,  g_V);
    cudaGetSymbolAddress((void**)&Vt, g_Vt);
    cudaGetSymbolAddress((void**)&S,  g_S);
    cudaGetSymbolAddress((void**)&Wt, g_Wt);

    cudaFuncSetAttribute(mm3nt, cudaFuncAttributeMaxDynamicSharedMemorySize, SMEM_BYTES);

    const dim3 blk(256);
    const dim3 tblk(32, 8);

    // 0) W^T (B operands must be [N,K] row-major)
    transpose_k<<<dim3(32, 32), tblk>>>(Wq, Wt,                          DIM, DIM);
    transpose_k<<<dim3(32, 32), tblk>>>(Wk, Wt + (size_t)DIM * DIM,     DIM, DIM);
    transpose_k<<<dim3(32, 32), tblk>>>(Wv, Wt + 2 * (size_t)DIM * DIM, DIM, DIM);

    // 1-3) projections: [4096,1024] = X @ Wt^T  (NT)
    const dim3 gp(DIM / 256, SEQ / 128);   // (4, 32)
    mm3nt<<<gp, blk, SMEM_BYTES>>>(X, Wt,                          Q, SEQ, DIM, DIM, 1.0f);
    mm3nt<<<gp, blk, SMEM_BYTES>>>(X, Wt + (size_t)DIM * DIM,      K, SEQ, DIM, DIM, 1.0f);
    mm3nt<<<gp, blk, SMEM_BYTES>>>(X, Wt + 2 * (size_t)DIM * DIM,  V, SEQ, DIM, DIM, 1.0f);

    // 4) V^T for the AV GEMM
    transpose_k<<<dim3(DIM / 32, SEQ / 32), tblk>>>(V, Vt, SEQ, DIM);

    // 5) S = (Q @ K^T) * 1/sqrt(DIM)
    mm3nt<<<dim3(SEQ / 256, SEQ / 128), blk, SMEM_BYTES>>>(Q, K, S, SEQ, SEQ, DIM, 0.03125f);

    // 6) softmax rows
    softmax_rows<<<SEQ, blk>>>(S, SEQ);

    // 7) out = S @ Vt^T
    mm3nt<<<dim3(DIM / 256, SEQ / 128), blk, SMEM_BYTES>>>(S, Vt, out, SEQ, DIM, SEQ, 1.0f);
}